// round 6
// baseline (speedup 1.0000x reference)
#include <cuda_runtime.h>
#include <math_constants.h>

#define FULLMASK 0xffffffffu

static constexpr int Bc = 4;
static constexpr int Nc = 4096;
static constexpr int S1 = 2048;
static constexpr int S2 = 512;
static constexpr int Kc = 64;

// ---------------- scratch (device globals; no allocation allowed) ----------------
__device__ float g_qpos1[Bc * S1 * 3];
__device__ float g_qpos2[Bc * S2 * 3];
__device__ int   g_nidx1[Bc * S1 * Kc];
__device__ int   g_nidx2[Bc * S2 * Kc];
__device__ int   g_cnt1[Bc * S1];
__device__ int   g_cnt2[Bc * S2];
__device__ float g_feat1[Bc * S1 * 64];
__device__ float g_bufA[Bc * S1 * Kc * 32];   // reused by layer2 (needs 131072*64 <= 16.8M floats)
__device__ float g_bufB[Bc * S1 * Kc * 32];

// ---------------- FPS: one block per batch, sequential argmax of min-dist ----------------
// Exactly mirrors the reference: start at index 0, each step d = ||p - cur||^2,
// min_d = min(min_d, d), next = argmax(min_d) with first-occurrence (lowest index)
// tie-break. Tie-break is encoded in a packed uint64 key: (d_bits << 32) | (n-1-idx),
// valid because min_d >= 0 so float bits are monotone.
template <int NPT, int NTH>
__global__ void fps_kernel(const float* __restrict__ pos, int pstride, int n, int nsamp,
                           float* __restrict__ qpos)
{
    const int b = blockIdx.x;
    const int t = threadIdx.x;
    const int lane = t & 31;
    const int warp = t >> 5;
    constexpr int NW = NTH / 32;

    const float* P = pos + (size_t)b * n * pstride;

    float px[NPT], py[NPT], pz[NPT], md[NPT];
    const int i0 = t * NPT;
#pragma unroll
    for (int k = 0; k < NPT; k++) {
        const float* p = P + (size_t)(i0 + k) * pstride;
        px[k] = p[0]; py[k] = p[1]; pz[k] = p[2];
        md[k] = CUDART_INF_F;
    }

    __shared__ unsigned long long wbest[NW];
    __shared__ float scur[3];
    if (t == 0) {
        float* o = qpos + (size_t)b * nsamp * 3;
        scur[0] = o[0] = P[0];
        scur[1] = o[1] = P[1];
        scur[2] = o[2] = P[2];
    }
    __syncthreads();
    float cx = scur[0], cy = scur[1], cz = scur[2];

    for (int step = 1; step < nsamp; step++) {
        float bm = -1.0f; int bi = 0;
#pragma unroll
        for (int k = 0; k < NPT; k++) {
            float dx = px[k] - cx, dy = py[k] - cy, dz = pz[k] - cz;
            float d = __fmaf_rn(dz, dz, __fmaf_rn(dy, dy, dx * dx));
            float m = fminf(md[k], d);
            md[k] = m;
            if (m > bm) { bm = m; bi = i0 + k; }   // strict > keeps lowest index on tie
        }
        unsigned long long key =
            ((unsigned long long)__float_as_uint(bm) << 32) | (unsigned)(n - 1 - bi);
#pragma unroll
        for (int off = 16; off; off >>= 1) {
            unsigned long long o = __shfl_down_sync(FULLMASK, key, off);
            if (o > key) key = o;
        }
        if (lane == 0) wbest[warp] = key;
        __syncthreads();
        if (t < 32) {
            unsigned long long k2 = (t < NW) ? wbest[t] : 0ull;
#pragma unroll
            for (int off = 16; off; off >>= 1) {
                unsigned long long o = __shfl_down_sync(FULLMASK, k2, off);
                if (o > k2) k2 = o;
            }
            if (t == 0) {
                int mi = n - 1 - (int)(unsigned)(k2 & 0xffffffffull);
                const float* p = P + (size_t)mi * pstride;
                float a = p[0], bb = p[1], c = p[2];
                scur[0] = a; scur[1] = bb; scur[2] = c;
                float* o = qpos + ((size_t)b * nsamp + step) * 3;
                o[0] = a; o[1] = bb; o[2] = c;
            }
        }
        __syncthreads();
        cx = scur[0]; cy = scur[1]; cz = scur[2];
    }
}

// ---------------- Ball query: warp per query, first K in-range points by ascending index ----------------
__global__ void ball_query_kernel(const float* __restrict__ pos, int pstride, int n,
                                  const float* __restrict__ qpos, int S, float r2,
                                  int* __restrict__ nidx, int* __restrict__ cnt_out,
                                  int totalq)
{
    int gw = (blockIdx.x * blockDim.x + threadIdx.x) >> 5;
    int lane = threadIdx.x & 31;
    if (gw >= totalq) return;
    int b = gw / S;
    const float* P = pos + (size_t)b * n * pstride;
    const float* q = qpos + (size_t)gw * 3;
    float qx = q[0], qy = q[1], qz = q[2];

    int cnt = 0;
    int* out = nidx + (size_t)gw * Kc;
    for (int base = 0; base < n && cnt < Kc; base += 32) {
        int i = base + lane;
        const float* p = P + (size_t)i * pstride;
        float dx = p[0] - qx, dy = p[1] - qy, dz = p[2] - qz;
        float d = __fmaf_rn(dz, dz, __fmaf_rn(dy, dy, dx * dx));
        bool in = (d <= r2);
        unsigned m = __ballot_sync(FULLMASK, in);
        int pre = __popc(m & ((1u << lane) - 1u));
        int slot = cnt + pre;
        if (in && slot < Kc) out[slot] = i;
        cnt += __popc(m);
    }
    if (cnt > Kc) cnt = Kc;
    for (int j = cnt + lane; j < Kc; j += 32) out[j] = 0;
    if (lane == 0) cnt_out[gw] = cnt;
}

// ---------------- Layer A: gather h0 = [nfeat, npos - qpos], then relu(h0 @ W + b) ----------------
template <int FDIM, int FSTRIDE, int FOFF, int PSTRIDE, int C1>
__global__ void __launch_bounds__(256)
layerA_kernel(const float* __restrict__ feat_src, const float* __restrict__ pos_src,
              int n, const float* __restrict__ qpos, int S,
              const int* __restrict__ nidx,
              const float* __restrict__ W, const float* __restrict__ bias,
              float* __restrict__ out, int nitems)
{
    constexpr int CIN = FDIM + 3;
    __shared__ __align__(16) float sW[CIN * C1];
    __shared__ float sB[C1];
    for (int i = threadIdx.x; i < CIN * C1; i += blockDim.x) sW[i] = W[i];
    for (int i = threadIdx.x; i < C1; i += blockDim.x) sB[i] = bias[i];
    __syncthreads();

    int t = blockIdx.x * blockDim.x + threadIdx.x;
    if (t >= nitems) return;
    int q = t >> 6;           // K = 64
    int b = q / S;
    int idx = nidx[t];

    float h0[CIN];
    const float* f = feat_src + ((size_t)b * n + idx) * FSTRIDE + FOFF;
    if constexpr ((FDIM % 4 == 0) && (FOFF % 4 == 0) && (FSTRIDE % 4 == 0)) {
#pragma unroll
        for (int k = 0; k < FDIM; k += 4) {
            float4 v = *reinterpret_cast<const float4*>(f + k);
            h0[k] = v.x; h0[k + 1] = v.y; h0[k + 2] = v.z; h0[k + 3] = v.w;
        }
    } else {
#pragma unroll
        for (int k = 0; k < FDIM; k++) h0[k] = f[k];
    }
    const float* pp = pos_src + ((size_t)b * n + idx) * PSTRIDE;
    const float* qq = qpos + (size_t)q * 3;
    h0[FDIM + 0] = pp[0] - qq[0];
    h0[FDIM + 1] = pp[1] - qq[1];
    h0[FDIM + 2] = pp[2] - qq[2];

    float* o = out + (size_t)t * C1;
#pragma unroll 1
    for (int cg = 0; cg < C1 / 4; cg++) {
        float a0 = sB[cg * 4 + 0], a1 = sB[cg * 4 + 1];
        float a2 = sB[cg * 4 + 2], a3 = sB[cg * 4 + 3];
#pragma unroll
        for (int k = 0; k < CIN; k++) {
            float4 w = *reinterpret_cast<const float4*>(&sW[k * C1 + cg * 4]);
            float h = h0[k];
            a0 = __fmaf_rn(h, w.x, a0); a1 = __fmaf_rn(h, w.y, a1);
            a2 = __fmaf_rn(h, w.z, a2); a3 = __fmaf_rn(h, w.w, a3);
        }
        *reinterpret_cast<float4*>(o + cg * 4) =
            make_float4(fmaxf(a0, 0.f), fmaxf(a1, 0.f), fmaxf(a2, 0.f), fmaxf(a3, 0.f));
    }
}

// ---------------- Layer B: relu(h @ W + b), item per thread ----------------
template <int C1, int C2>
__global__ void __launch_bounds__(256)
layerB_kernel(const float* __restrict__ in, const float* __restrict__ W,
              const float* __restrict__ bias, float* __restrict__ out, int nitems)
{
    __shared__ __align__(16) float sW[C1 * C2];
    __shared__ float sB[C2];
    for (int i = threadIdx.x; i < C1 * C2; i += blockDim.x) sW[i] = W[i];
    for (int i = threadIdx.x; i < C2; i += blockDim.x) sB[i] = bias[i];
    __syncthreads();

    int t = blockIdx.x * blockDim.x + threadIdx.x;
    if (t >= nitems) return;

    float h[C1];
    const float* f = in + (size_t)t * C1;
#pragma unroll
    for (int k = 0; k < C1; k += 4) {
        float4 v = *reinterpret_cast<const float4*>(f + k);
        h[k] = v.x; h[k + 1] = v.y; h[k + 2] = v.z; h[k + 3] = v.w;
    }
    float* o = out + (size_t)t * C2;
#pragma unroll 1
    for (int cg = 0; cg < C2 / 4; cg++) {
        float a0 = sB[cg * 4 + 0], a1 = sB[cg * 4 + 1];
        float a2 = sB[cg * 4 + 2], a3 = sB[cg * 4 + 3];
#pragma unroll
        for (int k = 0; k < C1; k++) {
            float4 w = *reinterpret_cast<const float4*>(&sW[k * C2 + cg * 4]);
            float hh = h[k];
            a0 = __fmaf_rn(hh, w.x, a0); a1 = __fmaf_rn(hh, w.y, a1);
            a2 = __fmaf_rn(hh, w.z, a2); a3 = __fmaf_rn(hh, w.w, a3);
        }
        *reinterpret_cast<float4*>(o + cg * 4) =
            make_float4(fmaxf(a0, 0.f), fmaxf(a1, 0.f), fmaxf(a2, 0.f), fmaxf(a3, 0.f));
    }
}

// ---------------- Layer C + masked max-pool: warp per query, lane = neighbor ----------------
template <int C2, int COUT, int NTH>
__global__ void __launch_bounds__(NTH)
layerC_kernel(const float* __restrict__ in, const int* __restrict__ cnt,
              const float* __restrict__ W, const float* __restrict__ bias,
              float* __restrict__ out, int totalq)
{
    constexpr int NW = NTH / 32;
    __shared__ __align__(16) float sW[C2 * COUT];
    __shared__ float sB[COUT];
    __shared__ float sOut[NW][COUT];
    for (int i = threadIdx.x; i < C2 * COUT; i += NTH) sW[i] = W[i];
    for (int i = threadIdx.x; i < COUT; i += NTH) sB[i] = bias[i];
    __syncthreads();

    int lane = threadIdx.x & 31;
    int wl = threadIdx.x >> 5;
    int q = blockIdx.x * NW + wl;
    if (q >= totalq) return;
    int c = cnt[q];

#pragma unroll 1
    for (int r = 0; r < 2; r++) {
        int j = r * 32 + lane;
        const float* f = in + ((size_t)q * Kc + j) * C2;
        float h[C2];
#pragma unroll
        for (int k = 0; k < C2; k += 4) {
            float4 v = *reinterpret_cast<const float4*>(f + k);
            h[k] = v.x; h[k + 1] = v.y; h[k + 2] = v.z; h[k + 3] = v.w;
        }
        bool valid = (j < c);
#pragma unroll 1
        for (int cg = 0; cg < COUT / 4; cg++) {
            float a0 = sB[cg * 4 + 0], a1 = sB[cg * 4 + 1];
            float a2 = sB[cg * 4 + 2], a3 = sB[cg * 4 + 3];
#pragma unroll
            for (int k = 0; k < C2; k++) {
                float4 w = *reinterpret_cast<const float4*>(&sW[k * COUT + cg * 4]);
                float hh = h[k];
                a0 = __fmaf_rn(hh, w.x, a0); a1 = __fmaf_rn(hh, w.y, a1);
                a2 = __fmaf_rn(hh, w.z, a2); a3 = __fmaf_rn(hh, w.w, a3);
            }
            a0 = fmaxf(a0, 0.f); a1 = fmaxf(a1, 0.f);
            a2 = fmaxf(a2, 0.f); a3 = fmaxf(a3, 0.f);
            if (!valid) { a0 = a1 = a2 = a3 = -CUDART_INF_F; }
#pragma unroll
            for (int off = 16; off; off >>= 1) {
                a0 = fmaxf(a0, __shfl_down_sync(FULLMASK, a0, off));
                a1 = fmaxf(a1, __shfl_down_sync(FULLMASK, a1, off));
                a2 = fmaxf(a2, __shfl_down_sync(FULLMASK, a2, off));
                a3 = fmaxf(a3, __shfl_down_sync(FULLMASK, a3, off));
            }
            if (lane == 0) {
                if (r == 0) {
                    sOut[wl][cg * 4 + 0] = a0; sOut[wl][cg * 4 + 1] = a1;
                    sOut[wl][cg * 4 + 2] = a2; sOut[wl][cg * 4 + 3] = a3;
                } else {
                    sOut[wl][cg * 4 + 0] = fmaxf(sOut[wl][cg * 4 + 0], a0);
                    sOut[wl][cg * 4 + 1] = fmaxf(sOut[wl][cg * 4 + 1], a1);
                    sOut[wl][cg * 4 + 2] = fmaxf(sOut[wl][cg * 4 + 2], a2);
                    sOut[wl][cg * 4 + 3] = fmaxf(sOut[wl][cg * 4 + 3], a3);
                }
            }
        }
    }
    __syncwarp();
    for (int c0 = lane; c0 < COUT; c0 += 32)
        out[(size_t)q * COUT + c0] = sOut[wl][c0];
}

// ---------------- Tail: optional pos / batch outputs (if harness concatenates tuple) ----------------
__global__ void tail_kernel(const float* __restrict__ qpos2, float* __restrict__ dout, int mode)
{
    int i = blockIdx.x * blockDim.x + threadIdx.x;
    const int featN = Bc * S2 * 128;
    const int posN = Bc * S2 * 3;
    if (i < posN) dout[featN + i] = qpos2[i];
    if (mode >= 2 && i < Bc * S2) dout[featN + posN + i] = (float)(i / S2);
}

extern "C" void kernel_launch(void* const* d_in, const int* in_sizes, int n_in,
                              void* d_out, int out_size)
{
    const float* x   = (const float*)d_in[0];
    const float* w1a = (const float*)d_in[1];  const float* b1a = (const float*)d_in[2];
    const float* w1b = (const float*)d_in[3];  const float* b1b = (const float*)d_in[4];
    const float* w1c = (const float*)d_in[5];  const float* b1c = (const float*)d_in[6];
    const float* w2a = (const float*)d_in[7];  const float* b2a = (const float*)d_in[8];
    const float* w2b = (const float*)d_in[9];  const float* b2b = (const float*)d_in[10];
    const float* w2c = (const float*)d_in[11]; const float* b2c = (const float*)d_in[12];
    float* out = (float*)d_out;

    void *pq1, *pq2, *pn1, *pn2, *pc1, *pc2, *pf1, *pa, *pb;
    cudaGetSymbolAddress(&pq1, g_qpos1);
    cudaGetSymbolAddress(&pq2, g_qpos2);
    cudaGetSymbolAddress(&pn1, g_nidx1);
    cudaGetSymbolAddress(&pn2, g_nidx2);
    cudaGetSymbolAddress(&pc1, g_cnt1);
    cudaGetSymbolAddress(&pc2, g_cnt2);
    cudaGetSymbolAddress(&pf1, g_feat1);
    cudaGetSymbolAddress(&pa, g_bufA);
    cudaGetSymbolAddress(&pb, g_bufB);
    float* qpos1 = (float*)pq1;  float* qpos2 = (float*)pq2;
    int* nidx1 = (int*)pn1;      int* nidx2 = (int*)pn2;
    int* cnt1 = (int*)pc1;       int* cnt2 = (int*)pc2;
    float* feat1 = (float*)pf1;  float* bufA = (float*)pa;  float* bufB = (float*)pb;

    // ---- Layer 1: N=4096 -> S1=2048, r^2=0.25, MLP 6->32->32->64 ----
    fps_kernel<16, 256><<<Bc, 256>>>(x, 6, Nc, S1, qpos1);
    ball_query_kernel<<<(Bc * S1 * 32) / 256, 256>>>(x, 6, Nc, qpos1, S1, 0.25f,
                                                     nidx1, cnt1, Bc * S1);
    layerA_kernel<3, 6, 3, 6, 32><<<(Bc * S1 * Kc) / 256, 256>>>(
        x, x, Nc, qpos1, S1, nidx1, w1a, b1a, bufA, Bc * S1 * Kc);
    layerB_kernel<32, 32><<<(Bc * S1 * Kc) / 256, 256>>>(bufA, w1b, b1b, bufB, Bc * S1 * Kc);
    layerC_kernel<32, 64, 256><<<(Bc * S1) / 8, 256>>>(bufB, cnt1, w1c, b1c, feat1, Bc * S1);

    // ---- Layer 2: S1=2048 -> S2=512, r^2=1.0, MLP 67->64->64->128 ----
    fps_kernel<8, 256><<<Bc, 256>>>(qpos1, 3, S1, S2, qpos2);
    ball_query_kernel<<<(Bc * S2 * 32) / 256, 256>>>(qpos1, 3, S1, qpos2, S2, 1.0f,
                                                     nidx2, cnt2, Bc * S2);
    layerA_kernel<64, 64, 0, 3, 64><<<(Bc * S2 * Kc) / 256, 256>>>(
        feat1, qpos1, S1, qpos2, S2, nidx2, w2a, b2a, bufA, Bc * S2 * Kc);
    layerB_kernel<64, 64><<<(Bc * S2 * Kc) / 256, 256>>>(bufA, w2b, b2b, bufB, Bc * S2 * Kc);
    layerC_kernel<64, 128, 256><<<(Bc * S2) / 8, 256>>>(bufB, cnt2, w2c, b2c, out, Bc * S2);

    // ---- Optional extra outputs if harness concatenated (feat, pos, batch) ----
    const int featN = Bc * S2 * 128;       // 262144
    const int posN = Bc * S2 * 3;          // 6144
    int mode = 0;
    if (out_size >= featN + posN) mode = 1;
    if (out_size >= featN + posN + Bc * S2) mode = 2;
    if (mode) {
        int tot = posN;
        tail_kernel<<<(tot + 255) / 256, 256>>>(qpos2, out, mode);
    }
}

// round 7
// speedup vs baseline: 1.4017x; 1.4017x over previous
#include <cuda_runtime.h>
#include <math_constants.h>

#define FULLMASK 0xffffffffu
typedef unsigned long long ull;

static constexpr int Bc = 4;
static constexpr int Nc = 4096;
static constexpr int S1 = 2048;
static constexpr int S2 = 512;
static constexpr int Kc = 64;

// ---------------- scratch (device globals; no allocation allowed) ----------------
__device__ float g_qpos1[Bc * S1 * 3];
__device__ float g_qpos2[Bc * S2 * 3];
__device__ int   g_nidx1[Bc * S1 * Kc];
__device__ int   g_nidx2[Bc * S2 * Kc];
__device__ int   g_cnt1[Bc * S1];
__device__ int   g_cnt2[Bc * S2];
__device__ float g_feat1[Bc * S1 * 64];
__device__ float g_bufA[Bc * S1 * Kc * 32];
__device__ float g_bufB[Bc * S1 * Kc * 32];

// ---------------- packed f32x2 helpers ----------------
__device__ __forceinline__ ull pk2(float lo, float hi) {
    ull r; asm("mov.b64 %0, {%1, %2};" : "=l"(r) : "f"(lo), "f"(hi)); return r;
}
__device__ __forceinline__ void upk2(float& lo, float& hi, ull v) {
    asm("mov.b64 {%0, %1}, %2;" : "=f"(lo), "=f"(hi) : "l"(v));
}
__device__ __forceinline__ ull fma2_(ull a, ull b, ull c) {
    ull d; asm("fma.rn.f32x2 %0, %1, %2, %3;" : "=l"(d) : "l"(a), "l"(b), "l"(c)); return d;
}
__device__ __forceinline__ ull add2_(ull a, ull b) {
    ull d; asm("add.rn.f32x2 %0, %1, %2;" : "=l"(d) : "l"(a), "l"(b)); return d;
}

// ---------------- FPS: one block per batch ----------------
// d = |p|^2 - 2 p.c + |c|^2 with |p|^2 precomputed; packed f32x2 distance math.
// Points cached in smem as float4(x,y,z,|p|^2) so the winner lookup is one LDS.128.
// One __syncthreads per step; skey double-buffered by step parity.
// Key packs (md_bits << 32) | (n-1-idx); md clamped >= 0 so bit order == float order,
// and argmax first-index tie-break matches jnp.argmax.
template <int NPT, int NTH>
__global__ void fps_kernel(const float* __restrict__ pos, int pstride, int n, int nsamp,
                           float* __restrict__ qpos)
{
    extern __shared__ float4 spts[];
    constexpr int NW = NTH / 32;
    __shared__ ull skey[2][NW];
    const int b = blockIdx.x, t = threadIdx.x, lane = t & 31, warp = t >> 5;
    const float* P = pos + (size_t)b * n * pstride;

    ull px2[NPT / 2], py2[NPT / 2], pz2[NPT / 2], nr2[NPT / 2];
    float md[NPT];
    const int i0 = t * NPT;
#pragma unroll
    for (int k2 = 0; k2 < NPT / 2; k2++) {
        const float* pA = P + (size_t)(i0 + 2 * k2) * pstride;
        const float* pB = pA + pstride;
        float ax = pA[0], ay = pA[1], az = pA[2];
        float bx = pB[0], by = pB[1], bz = pB[2];
        float na = __fmaf_rn(az, az, __fmaf_rn(ay, ay, ax * ax));
        float nb = __fmaf_rn(bz, bz, __fmaf_rn(by, by, bx * bx));
        px2[k2] = pk2(ax, bx); py2[k2] = pk2(ay, by);
        pz2[k2] = pk2(az, bz); nr2[k2] = pk2(na, nb);
        spts[i0 + 2 * k2]     = make_float4(ax, ay, az, na);
        spts[i0 + 2 * k2 + 1] = make_float4(bx, by, bz, nb);
        md[2 * k2] = CUDART_INF_F; md[2 * k2 + 1] = CUDART_INF_F;
    }
    __syncthreads();
    float4 c = spts[0];
    if (t == 0) { float* o = qpos + (size_t)b * nsamp * 3; o[0] = c.x; o[1] = c.y; o[2] = c.z; }

    for (int step = 1; step < nsamp; step++) {
        const ull KX = pk2(-2.f * c.x, -2.f * c.x);
        const ull KY = pk2(-2.f * c.y, -2.f * c.y);
        const ull KZ = pk2(-2.f * c.z, -2.f * c.z);
        const ull CC = pk2(c.w, c.w);
        float bm = -CUDART_INF_F; int bi = 0;
#pragma unroll
        for (int k2 = 0; k2 < NPT / 2; k2++) {
            ull e = fma2_(pz2[k2], KZ, nr2[k2]);
            e = fma2_(py2[k2], KY, e);
            e = fma2_(px2[k2], KX, e);
            e = add2_(e, CC);
            float e0, e1; upk2(e0, e1, e);
            float m0 = fminf(md[2 * k2], e0);     md[2 * k2] = m0;
            float m1 = fminf(md[2 * k2 + 1], e1); md[2 * k2 + 1] = m1;
            if (m0 > bm) { bm = m0; bi = i0 + 2 * k2; }
            if (m1 > bm) { bm = m1; bi = i0 + 2 * k2 + 1; }
        }
        bm = fmaxf(bm, 0.0f);   // guard packed-key order against cancellation negatives
        ull key = ((ull)__float_as_uint(bm) << 32) | (unsigned)(n - 1 - bi);
#pragma unroll
        for (int off = 16; off; off >>= 1) {
            ull o = __shfl_down_sync(FULLMASK, key, off);
            if (o > key) key = o;
        }
        if (lane == 0) skey[step & 1][warp] = key;
        __syncthreads();
        ull best = skey[step & 1][0];
#pragma unroll
        for (int w = 1; w < NW; w++) {
            ull o = skey[step & 1][w];
            if (o > best) best = o;
        }
        int wi = n - 1 - (int)(unsigned)(best & 0xffffffffull);
        c = spts[wi];
        if (t == 0) {
            float* o = qpos + ((size_t)b * nsamp + step) * 3;
            o[0] = c.x; o[1] = c.y; o[2] = c.z;
        }
    }
}

// ---------------- Ball query: warp per query, first K in-range by ascending index ----------------
__global__ void ball_query_kernel(const float* __restrict__ pos, int pstride, int n,
                                  const float* __restrict__ qpos, int S, float r2,
                                  int* __restrict__ nidx, int* __restrict__ cnt_out,
                                  int totalq)
{
    int gw = (blockIdx.x * blockDim.x + threadIdx.x) >> 5;
    int lane = threadIdx.x & 31;
    if (gw >= totalq) return;
    int b = gw / S;
    const float* P = pos + (size_t)b * n * pstride;
    const float* q = qpos + (size_t)gw * 3;
    float qx = q[0], qy = q[1], qz = q[2];

    int cnt = 0;
    int* out = nidx + (size_t)gw * Kc;
    for (int base = 0; base < n && cnt < Kc; base += 32) {
        int i = base + lane;
        const float* p = P + (size_t)i * pstride;
        float dx = p[0] - qx, dy = p[1] - qy, dz = p[2] - qz;
        float d = __fmaf_rn(dz, dz, __fmaf_rn(dy, dy, dx * dx));
        bool in = (d <= r2);
        unsigned m = __ballot_sync(FULLMASK, in);
        int pre = __popc(m & ((1u << lane) - 1u));
        int slot = cnt + pre;
        if (in && slot < Kc) out[slot] = i;
        cnt += __popc(m);
    }
    if (cnt > Kc) cnt = Kc;
    for (int j = cnt + lane; j < Kc; j += 32) out[j] = 0;
    if (lane == 0) cnt_out[gw] = cnt;
}

// ---------------- dense2: 2 items, packed-output FFMA2, relu, float4 stores ----------------
// out[c] = relu(b[c] + sum_k h[k]*W[k*COUT+c]); per k: 1 LDS.128 + 2 splats + 4 FFMA2 = 16 MAC.
template <int CIN, int COUT>
__device__ __forceinline__ void dense2(const float* ha, const float* hb,
                                       const float* sW, const float* sB,
                                       float4* __restrict__ oa, float4* __restrict__ ob)
{
#pragma unroll 1
    for (int cg = 0; cg < COUT / 4; cg++) {
        ull a01 = pk2(sB[cg * 4 + 0], sB[cg * 4 + 1]);
        ull a23 = pk2(sB[cg * 4 + 2], sB[cg * 4 + 3]);
        ull b01 = a01, b23 = a23;
#pragma unroll
        for (int k = 0; k < CIN; k++) {
            float4 w = *reinterpret_cast<const float4*>(&sW[k * COUT + cg * 4]);
            ull w01 = pk2(w.x, w.y), w23 = pk2(w.z, w.w);
            ull hA = pk2(ha[k], ha[k]);
            ull hB = pk2(hb[k], hb[k]);
            a01 = fma2_(hA, w01, a01); a23 = fma2_(hA, w23, a23);
            b01 = fma2_(hB, w01, b01); b23 = fma2_(hB, w23, b23);
        }
        float x0, x1, x2, x3, y0, y1, y2, y3;
        upk2(x0, x1, a01); upk2(x2, x3, a23);
        upk2(y0, y1, b01); upk2(y2, y3, b23);
        oa[cg] = make_float4(fmaxf(x0, 0.f), fmaxf(x1, 0.f), fmaxf(x2, 0.f), fmaxf(x3, 0.f));
        ob[cg] = make_float4(fmaxf(y0, 0.f), fmaxf(y1, 0.f), fmaxf(y2, 0.f), fmaxf(y3, 0.f));
    }
}

// ---------------- Stage1 fused A+B: gather -> 6->32 -> 32->32, 2 neighbors/thread ----------------
__global__ void __launch_bounds__(256)
layerAB1_kernel(const float* __restrict__ x, const float* __restrict__ qpos,
                const int* __restrict__ nidx,
                const float* __restrict__ W1, const float* __restrict__ B1,
                const float* __restrict__ W2, const float* __restrict__ B2,
                float* __restrict__ out, int npairs)
{
    __shared__ __align__(16) float sW1[6 * 32];
    __shared__ float sB1[32];
    __shared__ __align__(16) float sW2[32 * 32];
    __shared__ float sB2[32];
    for (int i = threadIdx.x; i < 6 * 32; i += blockDim.x) sW1[i] = W1[i];
    for (int i = threadIdx.x; i < 32; i += blockDim.x) { sB1[i] = B1[i]; sB2[i] = B2[i]; }
    for (int i = threadIdx.x; i < 32 * 32; i += blockDim.x) sW2[i] = W2[i];
    __syncthreads();

    int t = blockIdx.x * blockDim.x + threadIdx.x;
    if (t >= npairs) return;
    int ia = 2 * t;
    int q = ia >> 6;          // K = 64
    int b = q >> 11;          // S1 = 2048
    int idxa = nidx[ia], idxb = nidx[ia + 1];
    const float* ra = x + (size_t)(b * Nc + idxa) * 6;
    const float* rb = x + (size_t)(b * Nc + idxb) * 6;
    const float* qq = qpos + (size_t)q * 3;
    float qx = qq[0], qy = qq[1], qz = qq[2];

    float h0a[6] = { ra[3], ra[4], ra[5], ra[0] - qx, ra[1] - qy, ra[2] - qz };
    float h0b[6] = { rb[3], rb[4], rb[5], rb[0] - qx, rb[1] - qy, rb[2] - qz };

    float h1a[32], h1b[32];
    dense2<6, 32>(h0a, h0b, sW1, sB1, (float4*)h1a, (float4*)h1b);
    dense2<32, 32>(h1a, h1b, sW2, sB2,
                   (float4*)(out + (size_t)ia * 32),
                   (float4*)(out + (size_t)(ia + 1) * 32));
}

// ---------------- Stage2 layer A: gather [feat64, dpos3] -> 67->64, 2 items/thread ----------------
__global__ void __launch_bounds__(128)
layerA2_kernel(const float* __restrict__ feat1, const float* __restrict__ pos1,
               const float* __restrict__ qpos2, const int* __restrict__ nidx,
               const float* __restrict__ W, const float* __restrict__ Bb,
               float* __restrict__ out, int npairs)
{
    __shared__ __align__(16) float sW[67 * 64];
    __shared__ float sB[64];
    for (int i = threadIdx.x; i < 67 * 64; i += blockDim.x) sW[i] = W[i];
    for (int i = threadIdx.x; i < 64; i += blockDim.x) sB[i] = Bb[i];
    __syncthreads();

    int t = blockIdx.x * blockDim.x + threadIdx.x;
    if (t >= npairs) return;
    int ia = 2 * t;
    int q = ia >> 6;
    int b = q >> 9;           // S2 = 512
    int idxa = nidx[ia], idxb = nidx[ia + 1];
    const float* fa = feat1 + (size_t)(b * S1 + idxa) * 64;
    const float* fb = feat1 + (size_t)(b * S1 + idxb) * 64;
    const float* pa = pos1 + (size_t)(b * S1 + idxa) * 3;
    const float* pb = pos1 + (size_t)(b * S1 + idxb) * 3;
    const float* qq = qpos2 + (size_t)q * 3;
    float qx = qq[0], qy = qq[1], qz = qq[2];

    float h0a[67], h0b[67];
#pragma unroll
    for (int k = 0; k < 64; k += 4) {
        float4 va = *reinterpret_cast<const float4*>(fa + k);
        float4 vb = *reinterpret_cast<const float4*>(fb + k);
        h0a[k] = va.x; h0a[k + 1] = va.y; h0a[k + 2] = va.z; h0a[k + 3] = va.w;
        h0b[k] = vb.x; h0b[k + 1] = vb.y; h0b[k + 2] = vb.z; h0b[k + 3] = vb.w;
    }
    h0a[64] = pa[0] - qx; h0a[65] = pa[1] - qy; h0a[66] = pa[2] - qz;
    h0b[64] = pb[0] - qx; h0b[65] = pb[1] - qy; h0b[66] = pb[2] - qz;

    dense2<67, 64>(h0a, h0b, sW, sB,
                   (float4*)(out + (size_t)ia * 64),
                   (float4*)(out + (size_t)(ia + 1) * 64));
}

// ---------------- Stage2 layer B: 64->64, 2 items/thread ----------------
__global__ void __launch_bounds__(128)
layerB2_kernel(const float* __restrict__ in, const float* __restrict__ W,
               const float* __restrict__ Bb, float* __restrict__ out, int npairs)
{
    __shared__ __align__(16) float sW[64 * 64];
    __shared__ float sB[64];
    for (int i = threadIdx.x; i < 64 * 64; i += blockDim.x) sW[i] = W[i];
    for (int i = threadIdx.x; i < 64; i += blockDim.x) sB[i] = Bb[i];
    __syncthreads();

    int t = blockIdx.x * blockDim.x + threadIdx.x;
    if (t >= npairs) return;
    int ia = 2 * t;
    float ha[64], hb[64];
    const float* fa = in + (size_t)ia * 64;
    const float* fb = fa + 64;
#pragma unroll
    for (int k = 0; k < 64; k += 4) {
        float4 va = *reinterpret_cast<const float4*>(fa + k);
        float4 vb = *reinterpret_cast<const float4*>(fb + k);
        ha[k] = va.x; ha[k + 1] = va.y; ha[k + 2] = va.z; ha[k + 3] = va.w;
        hb[k] = vb.x; hb[k + 1] = vb.y; hb[k + 2] = vb.z; hb[k + 3] = vb.w;
    }
    dense2<64, 64>(ha, hb, sW, sB,
                   (float4*)(out + (size_t)ia * 64),
                   (float4*)(out + (size_t)(ia + 1) * 64));
}

// ---------------- Layer C + masked max-pool: warp/query, both neighbors resident ----------------
template <int C2, int COUT, int NTH>
__global__ void __launch_bounds__(NTH)
layerC_kernel(const float* __restrict__ in, const int* __restrict__ cnt,
              const float* __restrict__ W, const float* __restrict__ bias,
              float* __restrict__ out, int totalq)
{
    constexpr int NW = NTH / 32;
    __shared__ __align__(16) float sW[C2 * COUT];
    __shared__ float sB[COUT];
    for (int i = threadIdx.x; i < C2 * COUT; i += NTH) sW[i] = W[i];
    for (int i = threadIdx.x; i < COUT; i += NTH) sB[i] = bias[i];
    __syncthreads();

    int lane = threadIdx.x & 31;
    int wl = threadIdx.x >> 5;
    int q = blockIdx.x * NW + wl;
    if (q >= totalq) return;
    int c = cnt[q];
    bool va = lane < c, vb = lane + 32 < c;

    float ha[C2], hb[C2];
    const float* fa = in + ((size_t)q * Kc + lane) * C2;
    const float* fb = fa + 32 * C2;
#pragma unroll
    for (int k = 0; k < C2; k += 4) {
        float4 u = *reinterpret_cast<const float4*>(fa + k);
        float4 v = *reinterpret_cast<const float4*>(fb + k);
        ha[k] = u.x; ha[k + 1] = u.y; ha[k + 2] = u.z; ha[k + 3] = u.w;
        hb[k] = v.x; hb[k + 1] = v.y; hb[k + 2] = v.z; hb[k + 3] = v.w;
    }

#pragma unroll 1
    for (int cg = 0; cg < COUT / 4; cg++) {
        ull a01 = pk2(sB[cg * 4 + 0], sB[cg * 4 + 1]);
        ull a23 = pk2(sB[cg * 4 + 2], sB[cg * 4 + 3]);
        ull b01 = a01, b23 = a23;
#pragma unroll
        for (int k = 0; k < C2; k++) {
            float4 w = *reinterpret_cast<const float4*>(&sW[k * COUT + cg * 4]);
            ull w01 = pk2(w.x, w.y), w23 = pk2(w.z, w.w);
            ull hA = pk2(ha[k], ha[k]);
            ull hB = pk2(hb[k], hb[k]);
            a01 = fma2_(hA, w01, a01); a23 = fma2_(hA, w23, a23);
            b01 = fma2_(hB, w01, b01); b23 = fma2_(hB, w23, b23);
        }
        float x0, x1, x2, x3, y0, y1, y2, y3;
        upk2(x0, x1, a01); upk2(x2, x3, a23);
        upk2(y0, y1, b01); upk2(y2, y3, b23);
        x0 = va ? fmaxf(x0, 0.f) : -CUDART_INF_F;
        x1 = va ? fmaxf(x1, 0.f) : -CUDART_INF_F;
        x2 = va ? fmaxf(x2, 0.f) : -CUDART_INF_F;
        x3 = va ? fmaxf(x3, 0.f) : -CUDART_INF_F;
        y0 = vb ? fmaxf(y0, 0.f) : -CUDART_INF_F;
        y1 = vb ? fmaxf(y1, 0.f) : -CUDART_INF_F;
        y2 = vb ? fmaxf(y2, 0.f) : -CUDART_INF_F;
        y3 = vb ? fmaxf(y3, 0.f) : -CUDART_INF_F;
        float v0 = fmaxf(x0, y0), v1 = fmaxf(x1, y1);
        float v2 = fmaxf(x2, y2), v3 = fmaxf(x3, y3);
#pragma unroll
        for (int off = 16; off; off >>= 1) {
            v0 = fmaxf(v0, __shfl_down_sync(FULLMASK, v0, off));
            v1 = fmaxf(v1, __shfl_down_sync(FULLMASK, v1, off));
            v2 = fmaxf(v2, __shfl_down_sync(FULLMASK, v2, off));
            v3 = fmaxf(v3, __shfl_down_sync(FULLMASK, v3, off));
        }
        if (lane == 0)
            *reinterpret_cast<float4*>(out + (size_t)q * COUT + cg * 4) =
                make_float4(v0, v1, v2, v3);
    }
}

// ---------------- Tail: optional pos / batch outputs ----------------
__global__ void tail_kernel(const float* __restrict__ qpos2, float* __restrict__ dout, int mode)
{
    int i = blockIdx.x * blockDim.x + threadIdx.x;
    const int featN = Bc * S2 * 128;
    const int posN = Bc * S2 * 3;
    if (i < posN) dout[featN + i] = qpos2[i];
    if (mode >= 2 && i < Bc * S2) dout[featN + posN + i] = (float)(i / S2);
}

extern "C" void kernel_launch(void* const* d_in, const int* in_sizes, int n_in,
                              void* d_out, int out_size)
{
    const float* x   = (const float*)d_in[0];
    const float* w1a = (const float*)d_in[1];  const float* b1a = (const float*)d_in[2];
    const float* w1b = (const float*)d_in[3];  const float* b1b = (const float*)d_in[4];
    const float* w1c = (const float*)d_in[5];  const float* b1c = (const float*)d_in[6];
    const float* w2a = (const float*)d_in[7];  const float* b2a = (const float*)d_in[8];
    const float* w2b = (const float*)d_in[9];  const float* b2b = (const float*)d_in[10];
    const float* w2c = (const float*)d_in[11]; const float* b2c = (const float*)d_in[12];
    float* out = (float*)d_out;

    void *pq1, *pq2, *pn1, *pn2, *pc1, *pc2, *pf1, *pa, *pb;
    cudaGetSymbolAddress(&pq1, g_qpos1);
    cudaGetSymbolAddress(&pq2, g_qpos2);
    cudaGetSymbolAddress(&pn1, g_nidx1);
    cudaGetSymbolAddress(&pn2, g_nidx2);
    cudaGetSymbolAddress(&pc1, g_cnt1);
    cudaGetSymbolAddress(&pc2, g_cnt2);
    cudaGetSymbolAddress(&pf1, g_feat1);
    cudaGetSymbolAddress(&pa, g_bufA);
    cudaGetSymbolAddress(&pb, g_bufB);
    float* qpos1 = (float*)pq1;  float* qpos2 = (float*)pq2;
    int* nidx1 = (int*)pn1;      int* nidx2 = (int*)pn2;
    int* cnt1 = (int*)pc1;       int* cnt2 = (int*)pc2;
    float* feat1 = (float*)pf1;  float* bufA = (float*)pa;  float* bufB = (float*)pb;

    // fps1 needs 64KB dynamic smem (4096 float4)
    cudaFuncSetAttribute((const void*)fps_kernel<16, 256>,
                         cudaFuncAttributeMaxDynamicSharedMemorySize, Nc * 16);

    // ---- Stage 1: N=4096 -> S1=2048, r^2=0.25, MLP 6->32->32->64 ----
    fps_kernel<16, 256><<<Bc, 256, Nc * 16>>>(x, 6, Nc, S1, qpos1);
    ball_query_kernel<<<(Bc * S1 * 32) / 256, 256>>>(x, 6, Nc, qpos1, S1, 0.25f,
                                                     nidx1, cnt1, Bc * S1);
    layerAB1_kernel<<<(Bc * S1 * Kc / 2) / 256, 256>>>(
        x, qpos1, nidx1, w1a, b1a, w1b, b1b, bufB, Bc * S1 * Kc / 2);
    layerC_kernel<32, 64, 256><<<(Bc * S1) / 8, 256>>>(bufB, cnt1, w1c, b1c, feat1, Bc * S1);

    // ---- Stage 2: S1=2048 -> S2=512, r^2=1.0, MLP 67->64->64->128 ----
    fps_kernel<8, 256><<<Bc, 256, S1 * 16>>>(qpos1, 3, S1, S2, qpos2);
    ball_query_kernel<<<(Bc * S2 * 32) / 256, 256>>>(qpos1, 3, S1, qpos2, S2, 1.0f,
                                                     nidx2, cnt2, Bc * S2);
    layerA2_kernel<<<(Bc * S2 * Kc / 2) / 128, 128>>>(
        feat1, qpos1, qpos2, nidx2, w2a, b2a, bufA, Bc * S2 * Kc / 2);
    layerB2_kernel<<<(Bc * S2 * Kc / 2) / 128, 128>>>(bufA, w2b, b2b, bufB, Bc * S2 * Kc / 2);
    layerC_kernel<64, 128, 128><<<(Bc * S2) / 4, 128>>>(bufB, cnt2, w2c, b2c, out, Bc * S2);

    // ---- Optional extra outputs if harness concatenated (feat, pos, batch) ----
    const int featN = Bc * S2 * 128;
    const int posN = Bc * S2 * 3;
    int mode = 0;
    if (out_size >= featN + posN) mode = 1;
    if (out_size >= featN + posN + Bc * S2) mode = 2;
    if (mode) {
        tail_kernel<<<(posN + 255) / 256, 256>>>(qpos2, out, mode);
    }
}

// round 8
// speedup vs baseline: 1.5570x; 1.1107x over previous
#include <cuda_runtime.h>
#include <math_constants.h>

#define FULLMASK 0xffffffffu
typedef unsigned long long ull;

static constexpr int Bc = 4;
static constexpr int Nc = 4096;
static constexpr int S1 = 2048;
static constexpr int S2 = 512;
static constexpr int Kc = 64;

// ---------------- scratch (device globals; no allocation allowed) ----------------
__device__ float g_qpos1[Bc * S1 * 3];
__device__ float g_qpos2[Bc * S2 * 3];
__device__ int   g_nidx1[Bc * S1 * Kc];
__device__ int   g_nidx2[Bc * S2 * Kc];
__device__ int   g_cnt1[Bc * S1];
__device__ int   g_cnt2[Bc * S2];
__device__ float g_feat1[Bc * S1 * 64];
__device__ float g_bufA[Bc * S1 * Kc * 32];
__device__ float g_bufB[Bc * S1 * Kc * 32];

// ---------------- packed f32x2 helpers ----------------
__device__ __forceinline__ ull pk2(float lo, float hi) {
    ull r; asm("mov.b64 %0, {%1, %2};" : "=l"(r) : "f"(lo), "f"(hi)); return r;
}
__device__ __forceinline__ void upk2(float& lo, float& hi, ull v) {
    asm("mov.b64 {%0, %1}, %2;" : "=f"(lo), "=f"(hi) : "l"(v));
}
__device__ __forceinline__ ull fma2_(ull a, ull b, ull c) {
    ull d; asm("fma.rn.f32x2 %0, %1, %2, %3;" : "=l"(d) : "l"(a), "l"(b), "l"(c)); return d;
}
__device__ __forceinline__ ull add2_(ull a, ull b) {
    ull d; asm("add.rn.f32x2 %0, %1, %2;" : "=l"(d) : "l"(a), "l"(b)); return d;
}

// ---------------- FPS body: one block per batch ----------------
// d = |p|^2 - 2 p.c + |c|^2 (|p|^2 precomputed), packed f32x2 math.
// Warp reduction via 2 dependent redux.sync.max.u32 (value, then n-1-idx among
// lanes matching the max) -> same lowest-index tie-break as jnp.argmax.
// skey double-buffered by step parity; one __syncthreads per step.
template <int NPT, int NTH>
__device__ __forceinline__ void fps_body(const float* __restrict__ pos, int pstride,
                                         int n, int nsamp, float* __restrict__ qpos, int b)
{
    extern __shared__ float4 spts[];
    constexpr int NW = NTH / 32;
    __shared__ ull skey[2][NW];
    const int t = threadIdx.x, lane = t & 31, warp = t >> 5;
    const float* P = pos + (size_t)b * n * pstride;

    ull px2[NPT / 2], py2[NPT / 2], pz2[NPT / 2], nr2[NPT / 2];
    float md[NPT];
    const int i0 = t * NPT;
#pragma unroll
    for (int k2 = 0; k2 < NPT / 2; k2++) {
        const float* pA = P + (size_t)(i0 + 2 * k2) * pstride;
        const float* pB = pA + pstride;
        float ax = pA[0], ay = pA[1], az = pA[2];
        float bx = pB[0], by = pB[1], bz = pB[2];
        float na = __fmaf_rn(az, az, __fmaf_rn(ay, ay, ax * ax));
        float nb = __fmaf_rn(bz, bz, __fmaf_rn(by, by, bx * bx));
        px2[k2] = pk2(ax, bx); py2[k2] = pk2(ay, by);
        pz2[k2] = pk2(az, bz); nr2[k2] = pk2(na, nb);
        spts[i0 + 2 * k2]     = make_float4(ax, ay, az, na);
        spts[i0 + 2 * k2 + 1] = make_float4(bx, by, bz, nb);
        md[2 * k2] = CUDART_INF_F; md[2 * k2 + 1] = CUDART_INF_F;
    }
    __syncthreads();
    float4 c = spts[0];
    if (t == 0) { float* o = qpos + (size_t)b * nsamp * 3; o[0] = c.x; o[1] = c.y; o[2] = c.z; }

    for (int step = 1; step < nsamp; step++) {
        const ull KX = pk2(-2.f * c.x, -2.f * c.x);
        const ull KY = pk2(-2.f * c.y, -2.f * c.y);
        const ull KZ = pk2(-2.f * c.z, -2.f * c.z);
        const ull CC = pk2(c.w, c.w);
        float bm = -CUDART_INF_F; int bi = 0;
#pragma unroll
        for (int k2 = 0; k2 < NPT / 2; k2++) {
            ull e = fma2_(pz2[k2], KZ, nr2[k2]);
            e = fma2_(py2[k2], KY, e);
            e = fma2_(px2[k2], KX, e);
            e = add2_(e, CC);
            float e0, e1; upk2(e0, e1, e);
            float m0 = fminf(md[2 * k2], e0);     md[2 * k2] = m0;
            float m1 = fminf(md[2 * k2 + 1], e1); md[2 * k2 + 1] = m1;
            if (m0 > bm) { bm = m0; bi = i0 + 2 * k2; }
            if (m1 > bm) { bm = m1; bi = i0 + 2 * k2 + 1; }
        }
        bm = fmaxf(bm, 0.0f);   // keep unsigned bit order valid
        unsigned hbits = __float_as_uint(bm);
        unsigned hmax = __reduce_max_sync(FULLMASK, hbits);
        unsigned locand = (hbits == hmax) ? (unsigned)(n - 1 - bi) : 0u;
        unsigned lomax = __reduce_max_sync(FULLMASK, locand);
        if (lane == 0) skey[step & 1][warp] = ((ull)hmax << 32) | lomax;
        __syncthreads();
        ull best = skey[step & 1][0];
#pragma unroll
        for (int w = 1; w < NW; w++) {
            ull o = skey[step & 1][w];
            if (o > best) best = o;
        }
        int wi = n - 1 - (int)(unsigned)(best & 0xffffffffull);
        c = spts[wi];
        if (t == 0) {
            float* o = qpos + ((size_t)b * nsamp + step) * 3;
            o[0] = c.x; o[1] = c.y; o[2] = c.z;
        }
    }
}

template <int NPT, int NTH>
__global__ void fps_kernel(const float* __restrict__ pos, int pstride, int n, int nsamp,
                           float* __restrict__ qpos)
{
    fps_body<NPT, NTH>(pos, pstride, n, nsamp, qpos, blockIdx.x);
}

// ---------------- Ball query body: warp per query, first K in-range by index ----------------
__device__ __forceinline__ void ball_body(const float* __restrict__ pos, int pstride, int n,
                                          const float* __restrict__ qpos, int S, float r2,
                                          int* __restrict__ nidx, int* __restrict__ cnt_out,
                                          int totalq, int gw)
{
    int lane = threadIdx.x & 31;
    if (gw >= totalq) return;
    int b = gw / S;
    const float* P = pos + (size_t)b * n * pstride;
    const float* q = qpos + (size_t)gw * 3;
    float qx = q[0], qy = q[1], qz = q[2];

    int cnt = 0;
    int* out = nidx + (size_t)gw * Kc;
    for (int base = 0; base < n && cnt < Kc; base += 32) {
        int i = base + lane;
        const float* p = P + (size_t)i * pstride;
        float dx = p[0] - qx, dy = p[1] - qy, dz = p[2] - qz;
        float d = __fmaf_rn(dz, dz, __fmaf_rn(dy, dy, dx * dx));
        bool in = (d <= r2);
        unsigned m = __ballot_sync(FULLMASK, in);
        int pre = __popc(m & ((1u << lane) - 1u));
        int slot = cnt + pre;
        if (in && slot < Kc) out[slot] = i;
        cnt += __popc(m);
    }
    if (cnt > Kc) cnt = Kc;
    for (int j = cnt + lane; j < Kc; j += 32) out[j] = 0;
    if (lane == 0) cnt_out[gw] = cnt;
}

// ---------------- K2: fps2 (blocks 0..3) || ball1 (rest); dyn smem 32KB for fps ----------------
__global__ void __launch_bounds__(256)
k2_fps2_ball1(const float* __restrict__ x, const float* __restrict__ qpos1,
              float* __restrict__ qpos2,
              int* __restrict__ nidx1, int* __restrict__ cnt1)
{
    if (blockIdx.x < Bc) {
        fps_body<8, 256>(qpos1, 3, S1, S2, qpos2, blockIdx.x);
    } else {
        int gw = (blockIdx.x - Bc) * 8 + (threadIdx.x >> 5);
        ball_body(x, 6, Nc, qpos1, S1, 0.25f, nidx1, cnt1, Bc * S1, gw);
    }
}

// ---------------- dense1: 1 item, packed-output FFMA2, relu, float4 stores ----------------
template <int CIN, int COUT>
__device__ __forceinline__ void dense1(const float* h, const float* sW, const float* sB,
                                       float4* __restrict__ o)
{
#pragma unroll 1
    for (int cg = 0; cg < COUT / 4; cg++) {
        ull a01 = pk2(sB[cg * 4 + 0], sB[cg * 4 + 1]);
        ull a23 = pk2(sB[cg * 4 + 2], sB[cg * 4 + 3]);
#pragma unroll
        for (int k = 0; k < CIN; k++) {
            float4 w = *reinterpret_cast<const float4*>(&sW[k * COUT + cg * 4]);
            ull hh = pk2(h[k], h[k]);
            a01 = fma2_(hh, pk2(w.x, w.y), a01);
            a23 = fma2_(hh, pk2(w.z, w.w), a23);
        }
        float x0, x1, x2, x3;
        upk2(x0, x1, a01); upk2(x2, x3, a23);
        o[cg] = make_float4(fmaxf(x0, 0.f), fmaxf(x1, 0.f), fmaxf(x2, 0.f), fmaxf(x3, 0.f));
    }
}

// ---------------- K3: ball2 (first 256 blocks) || fused stage1 A+B (1 item/thread) ----------------
static constexpr int BALL2_BLKS = (Bc * S2) / 4;   // 2048 warps at 4 warps/128-thr block = 512 blocks
__global__ void __launch_bounds__(128)
k3_ball2_ab1(const float* __restrict__ x, const float* __restrict__ qpos1,
             const float* __restrict__ qpos2,
             int* __restrict__ nidx2, int* __restrict__ cnt2,
             const int* __restrict__ nidx1,
             const float* __restrict__ W1, const float* __restrict__ B1,
             const float* __restrict__ W2, const float* __restrict__ B2,
             float* __restrict__ out)
{
    if (blockIdx.x < BALL2_BLKS) {
        int gw = blockIdx.x * 4 + (threadIdx.x >> 5);
        ball_body(qpos1, 3, S1, qpos2, S2, 1.0f, nidx2, cnt2, Bc * S2, gw);
        return;
    }
    __shared__ __align__(16) float sW1[6 * 32];
    __shared__ float sB1[32];
    __shared__ __align__(16) float sW2[32 * 32];
    __shared__ float sB2[32];
    for (int i = threadIdx.x; i < 6 * 32; i += 128) sW1[i] = W1[i];
    if (threadIdx.x < 32) { sB1[threadIdx.x] = B1[threadIdx.x]; sB2[threadIdx.x] = B2[threadIdx.x]; }
    for (int i = threadIdx.x; i < 32 * 32; i += 128) sW2[i] = W2[i];
    __syncthreads();

    int t = (blockIdx.x - BALL2_BLKS) * 128 + threadIdx.x;   // item index
    int q = t >> 6;
    int b = q >> 11;
    int idx = nidx1[t];
    const float* r = x + (size_t)(b * Nc + idx) * 6;
    const float* qq = qpos1 + (size_t)q * 3;
    float h0[6] = { r[3], r[4], r[5], r[0] - qq[0], r[1] - qq[1], r[2] - qq[2] };
    float h1[32];
    dense1<6, 32>(h0, sW1, sB1, (float4*)h1);
    dense1<32, 32>(h1, sW2, sB2, (float4*)(out + (size_t)t * 32));
}

// ---------------- Stage2 layer A: gather [feat64, dpos3] -> 67->64, 1 item/thread ----------------
__global__ void __launch_bounds__(128)
layerA2_kernel(const float* __restrict__ feat1, const float* __restrict__ pos1,
               const float* __restrict__ qpos2, const int* __restrict__ nidx,
               const float* __restrict__ W, const float* __restrict__ Bb,
               float* __restrict__ out)
{
    __shared__ __align__(16) float sW[67 * 64];
    __shared__ float sB[64];
    for (int i = threadIdx.x; i < 67 * 64; i += 128) sW[i] = W[i];
    if (threadIdx.x < 64) sB[threadIdx.x] = Bb[threadIdx.x];
    __syncthreads();

    int t = blockIdx.x * 128 + threadIdx.x;
    int q = t >> 6;
    int b = q >> 9;
    int idx = nidx[t];
    const float* f = feat1 + (size_t)(b * S1 + idx) * 64;
    const float* pp = pos1 + (size_t)(b * S1 + idx) * 3;
    const float* qq = qpos2 + (size_t)q * 3;

    float h0[67];
#pragma unroll
    for (int k = 0; k < 64; k += 4) {
        float4 v = *reinterpret_cast<const float4*>(f + k);
        h0[k] = v.x; h0[k + 1] = v.y; h0[k + 2] = v.z; h0[k + 3] = v.w;
    }
    h0[64] = pp[0] - qq[0]; h0[65] = pp[1] - qq[1]; h0[66] = pp[2] - qq[2];
    dense1<67, 64>(h0, sW, sB, (float4*)(out + (size_t)t * 64));
}

// ---------------- Stage2 layer B: 64->64, 1 item/thread ----------------
__global__ void __launch_bounds__(128)
layerB2_kernel(const float* __restrict__ in, const float* __restrict__ W,
               const float* __restrict__ Bb, float* __restrict__ out)
{
    __shared__ __align__(16) float sW[64 * 64];
    __shared__ float sB[64];
    for (int i = threadIdx.x; i < 64 * 64; i += 128) sW[i] = W[i];
    if (threadIdx.x < 64) sB[threadIdx.x] = Bb[threadIdx.x];
    __syncthreads();

    int t = blockIdx.x * 128 + threadIdx.x;
    float h[64];
    const float* f = in + (size_t)t * 64;
#pragma unroll
    for (int k = 0; k < 64; k += 4) {
        float4 v = *reinterpret_cast<const float4*>(f + k);
        h[k] = v.x; h[k + 1] = v.y; h[k + 2] = v.z; h[k + 3] = v.w;
    }
    dense1<64, 64>(h, sW, sB, (float4*)(out + (size_t)t * 64));
}

// ---------------- Layer C + masked max-pool: warp/query, both neighbors resident ----------------
// TAILB extra blocks (beyond totalq/NWq) write the optional pos/batch outputs.
template <int C2, int COUT, int NTH, bool TAIL>
__global__ void __launch_bounds__(NTH)
layerC_kernel(const float* __restrict__ in, const int* __restrict__ cnt,
              const float* __restrict__ W, const float* __restrict__ bias,
              float* __restrict__ out, int totalq,
              const float* __restrict__ qpos2, int mode)
{
    constexpr int NW = NTH / 32;
    if (TAIL && (int)blockIdx.x >= totalq / NW) {
        if (mode) {
            int i = ((int)blockIdx.x - totalq / NW) * NTH + threadIdx.x;
            const int featN = Bc * S2 * 128;
            const int posN = Bc * S2 * 3;
            if (i < posN) out[featN + i] = qpos2[i];
            if (mode >= 2 && i < Bc * S2) out[featN + posN + i] = (float)(i / S2);
        }
        return;
    }
    __shared__ __align__(16) float sW[C2 * COUT];
    __shared__ float sB[COUT];
    for (int i = threadIdx.x; i < C2 * COUT; i += NTH) sW[i] = W[i];
    for (int i = threadIdx.x; i < COUT; i += NTH) sB[i] = bias[i];
    __syncthreads();

    int lane = threadIdx.x & 31;
    int wl = threadIdx.x >> 5;
    int q = blockIdx.x * NW + wl;
    if (q >= totalq) return;
    int c = cnt[q];
    bool va = lane < c, vb = lane + 32 < c;

    float ha[C2], hb[C2];
    const float* fa = in + ((size_t)q * Kc + lane) * C2;
    const float* fb = fa + 32 * C2;
#pragma unroll
    for (int k = 0; k < C2; k += 4) {
        float4 u = *reinterpret_cast<const float4*>(fa + k);
        float4 v = *reinterpret_cast<const float4*>(fb + k);
        ha[k] = u.x; ha[k + 1] = u.y; ha[k + 2] = u.z; ha[k + 3] = u.w;
        hb[k] = v.x; hb[k + 1] = v.y; hb[k + 2] = v.z; hb[k + 3] = v.w;
    }

#pragma unroll 1
    for (int cg = 0; cg < COUT / 4; cg++) {
        ull a01 = pk2(sB[cg * 4 + 0], sB[cg * 4 + 1]);
        ull a23 = pk2(sB[cg * 4 + 2], sB[cg * 4 + 3]);
        ull b01 = a01, b23 = a23;
#pragma unroll
        for (int k = 0; k < C2; k++) {
            float4 w = *reinterpret_cast<const float4*>(&sW[k * COUT + cg * 4]);
            ull w01 = pk2(w.x, w.y), w23 = pk2(w.z, w.w);
            ull hA = pk2(ha[k], ha[k]);
            ull hB = pk2(hb[k], hb[k]);
            a01 = fma2_(hA, w01, a01); a23 = fma2_(hA, w23, a23);
            b01 = fma2_(hB, w01, b01); b23 = fma2_(hB, w23, b23);
        }
        float x0, x1, x2, x3, y0, y1, y2, y3;
        upk2(x0, x1, a01); upk2(x2, x3, a23);
        upk2(y0, y1, b01); upk2(y2, y3, b23);
        x0 = va ? fmaxf(x0, 0.f) : -CUDART_INF_F;
        x1 = va ? fmaxf(x1, 0.f) : -CUDART_INF_F;
        x2 = va ? fmaxf(x2, 0.f) : -CUDART_INF_F;
        x3 = va ? fmaxf(x3, 0.f) : -CUDART_INF_F;
        y0 = vb ? fmaxf(y0, 0.f) : -CUDART_INF_F;
        y1 = vb ? fmaxf(y1, 0.f) : -CUDART_INF_F;
        y2 = vb ? fmaxf(y2, 0.f) : -CUDART_INF_F;
        y3 = vb ? fmaxf(y3, 0.f) : -CUDART_INF_F;
        float v0 = fmaxf(x0, y0), v1 = fmaxf(x1, y1);
        float v2 = fmaxf(x2, y2), v3 = fmaxf(x3, y3);
#pragma unroll
        for (int off = 16; off; off >>= 1) {
            v0 = fmaxf(v0, __shfl_down_sync(FULLMASK, v0, off));
            v1 = fmaxf(v1, __shfl_down_sync(FULLMASK, v1, off));
            v2 = fmaxf(v2, __shfl_down_sync(FULLMASK, v2, off));
            v3 = fmaxf(v3, __shfl_down_sync(FULLMASK, v3, off));
        }
        if (lane == 0)
            *reinterpret_cast<float4*>(out + (size_t)q * COUT + cg * 4) =
                make_float4(v0, v1, v2, v3);
    }
}

extern "C" void kernel_launch(void* const* d_in, const int* in_sizes, int n_in,
                              void* d_out, int out_size)
{
    const float* x   = (const float*)d_in[0];
    const float* w1a = (const float*)d_in[1];  const float* b1a = (const float*)d_in[2];
    const float* w1b = (const float*)d_in[3];  const float* b1b = (const float*)d_in[4];
    const float* w1c = (const float*)d_in[5];  const float* b1c = (const float*)d_in[6];
    const float* w2a = (const float*)d_in[7];  const float* b2a = (const float*)d_in[8];
    const float* w2b = (const float*)d_in[9];  const float* b2b = (const float*)d_in[10];
    const float* w2c = (const float*)d_in[11]; const float* b2c = (const float*)d_in[12];
    float* out = (float*)d_out;

    void *pq1, *pq2, *pn1, *pn2, *pc1, *pc2, *pf1, *pa, *pb;
    cudaGetSymbolAddress(&pq1, g_qpos1);
    cudaGetSymbolAddress(&pq2, g_qpos2);
    cudaGetSymbolAddress(&pn1, g_nidx1);
    cudaGetSymbolAddress(&pn2, g_nidx2);
    cudaGetSymbolAddress(&pc1, g_cnt1);
    cudaGetSymbolAddress(&pc2, g_cnt2);
    cudaGetSymbolAddress(&pf1, g_feat1);
    cudaGetSymbolAddress(&pa, g_bufA);
    cudaGetSymbolAddress(&pb, g_bufB);
    float* qpos1 = (float*)pq1;  float* qpos2 = (float*)pq2;
    int* nidx1 = (int*)pn1;      int* nidx2 = (int*)pn2;
    int* cnt1 = (int*)pc1;       int* cnt2 = (int*)pc2;
    float* feat1 = (float*)pf1;  float* bufA = (float*)pa;  float* bufB = (float*)pb;

    // fps1 needs 64KB dynamic smem (4096 float4)
    cudaFuncSetAttribute((const void*)fps_kernel<16, 256>,
                         cudaFuncAttributeMaxDynamicSharedMemorySize, Nc * 16);

    const int featN = Bc * S2 * 128;
    const int posN = Bc * S2 * 3;
    int mode = 0;
    if (out_size >= featN + posN) mode = 1;
    if (out_size >= featN + posN + Bc * S2) mode = 2;

    // K1: fps stage1 (N=4096 -> S1=2048)
    fps_kernel<16, 256><<<Bc, 256, Nc * 16>>>(x, 6, Nc, S1, qpos1);

    // K2: fps stage2 (S1 -> S2) overlapped with ball query stage1
    {
        int ballBlks = (Bc * S1) / 8;           // 8 warps per 256-thr block
        k2_fps2_ball1<<<Bc + ballBlks, 256, S1 * 16>>>(x, qpos1, qpos2, nidx1, cnt1);
    }

    // K3: ball query stage2 overlapped with fused stage1 MLP A+B (1 item/thread)
    {
        int abBlks = (Bc * S1 * Kc) / 128;      // 4096
        k3_ball2_ab1<<<BALL2_BLKS + abBlks, 128>>>(x, qpos1, qpos2, nidx2, cnt2,
                                                   nidx1, w1a, b1a, w1b, b1b, bufB);
    }

    // K4: stage1 layer C + maxpool
    layerC_kernel<32, 64, 128, false><<<(Bc * S1) / 4, 128>>>(
        bufB, cnt1, w1c, b1c, feat1, Bc * S1, nullptr, 0);

    // K5/K6: stage2 MLP A, B (1 item/thread)
    layerA2_kernel<<<(Bc * S2 * Kc) / 128, 128>>>(feat1, qpos1, qpos2, nidx2, w2a, b2a, bufA);
    layerB2_kernel<<<(Bc * S2 * Kc) / 128, 128>>>(bufA, w2b, b2b, bufB);

    // K7: stage2 layer C + maxpool, with tail blocks for optional pos/batch outputs
    {
        int nq = (Bc * S2) / 4;                 // 512 query blocks
        int tailBlks = (posN + 127) / 128 + 1;  // covers pos floats (and batch ints)
        layerC_kernel<64, 128, 128, true><<<nq + tailBlks, 128>>>(
            bufB, cnt2, w2c, b2c, out, Bc * S2, qpos2, mode);
    }
}